// round 14
// baseline (speedup 1.0000x reference)
#include <cuda_runtime.h>
#include <cuda_fp16.h>
#include <cuda_fp8.h>
#include <cstdint>
#include <math.h>

#define NN 50000
#define EE 800000
#define F_IN 58
#define FP 64
#define H1 300
#define H2 100
#define H1P 320
#define H2P 128
#define KA1 128   // GEMM1 K: [xp|tx1]
#define KH 320    // padded K for stage-2 GEMMs
#define M2B 256   // W2c cols: [W2_1 | W2_0]
#define ZSB 112   // z row stride in BYTES (fp8); cols 100..111 == 0

// ---------------------------------------------------------------------------
// Scratch (device-global, no runtime allocation).
// ---------------------------------------------------------------------------
struct alignas(16) Scratch {
    int   deg[NN];
    int   cnt[NN];
    int   rowptr[NN + 4];
    int   cursor[NN];
    int2  csr_sn[EE];        // packed (src, norm-bits), CSR(dst) order
    int   bsum[64];
    int   done[4];
    float dis[NN];
    __half xpA[NN * KA1];    // [x_fp16 | Agg(x)] fp16
    __half h_fp[NN * KH];    // relu(cheb1) fp16 [N,320]
    __half hW21f[NN * H2P];  // h @ W2_1 (fp16)
    __half hW20h[NN * H2P];  // h @ W2_0 (fp16)
    __half agg2h[NN * H2P];  // Agg(hW21f) fp16
    uint8_t z8[NN * ZSB];    // compact fp8(e4m3) z
    __half W1c[KA1 * H1P];
    __half W2c[KH * M2B];
    __half L1[FP * H2P];
    __half L2[FP * H2P];
    float b1p[H1P], b2p[H2P], l1bp[H2P], l2bp[H2P];
    float w30p[H2P], w31p[H2P];
    float s0[NN], s1[NN];
    float accum[2];
};
__device__ Scratch g_s;

// ---------------------------------------------------------------------------
// PTX helpers
// ---------------------------------------------------------------------------
__device__ __forceinline__ uint32_t smem_u32(const void* p) {
    return (uint32_t)__cvta_generic_to_shared(p);
}
__device__ __forceinline__ void ldm_x4(uint32_t* r, uint32_t addr) {
    asm volatile("ldmatrix.sync.aligned.m8n8.x4.shared.b16 {%0,%1,%2,%3}, [%4];"
                 : "=r"(r[0]), "=r"(r[1]), "=r"(r[2]), "=r"(r[3]) : "r"(addr));
}
__device__ __forceinline__ void ldm_x4_t(uint32_t* r, uint32_t addr) {
    asm volatile("ldmatrix.sync.aligned.m8n8.x4.trans.shared.b16 {%0,%1,%2,%3}, [%4];"
                 : "=r"(r[0]), "=r"(r[1]), "=r"(r[2]), "=r"(r[3]) : "r"(addr));
}
__device__ __forceinline__ void mma_fp16(float* c, const uint32_t* a, const uint32_t* b) {
    asm volatile("mma.sync.aligned.m16n8k16.row.col.f32.f16.f16.f32 "
                 "{%0,%1,%2,%3}, {%4,%5,%6,%7}, {%8,%9}, {%0,%1,%2,%3};"
                 : "+f"(c[0]), "+f"(c[1]), "+f"(c[2]), "+f"(c[3])
                 : "r"(a[0]), "r"(a[1]), "r"(a[2]), "r"(a[3]), "r"(b[0]), "r"(b[1]));
}
__device__ __forceinline__ void cp_async16(uint32_t dst, const void* src, bool pred) {
    int sz = pred ? 16 : 0;
    asm volatile("cp.async.cg.shared.global [%0], [%1], 16, %2;\n"
                 :: "r"(dst), "l"(src), "r"(sz));
}
__device__ __forceinline__ void cp_commit() {
    asm volatile("cp.async.commit_group;\n");
}
template <int N>
__device__ __forceinline__ void cp_wait() {
    asm volatile("cp.async.wait_group %0;\n" :: "n"(N));
}

// ---------------------------------------------------------------------------
// zero_kernel: tiny, runs FIRST (ordering anchor for the atomics that follow).
// ---------------------------------------------------------------------------
__global__ void zero_kernel(int n) {
    int i = blockIdx.x * blockDim.x + threadIdx.x;
    if (i < n) { g_s.deg[i] = 0; g_s.cnt[i] = 0; g_s.s0[i] = 0.f; g_s.s1[i] = 0.f; }
    if (i < 2) g_s.accum[i] = 0.f;
    if (i == 0) g_s.done[0] = 0;
}

// ---------------------------------------------------------------------------
// setup2: hist blocks [0,nbE) ∥ pad-x blocks [nbE,nbE+nbA) ∥ conv blocks rest.
// Race-free: zeroing happened in the previous launch; all writes independent.
// ---------------------------------------------------------------------------
#define CN1 (KA1 * H1P)
#define CN2 (KH * M2B)
#define CN3 (FP * H2P)
#define CTOT (CN1 + CN2 + 2 * CN3 + H1P + 5 * H2P)
__global__ void setup2_kernel(const float* __restrict__ x,
                              const int* __restrict__ src, const int* __restrict__ dst,
                              const float* __restrict__ W10, const float* __restrict__ W11,
                              const float* __restrict__ W20, const float* __restrict__ W21,
                              const float* __restrict__ l1W, const float* __restrict__ l2W,
                              const float* __restrict__ b1, const float* __restrict__ b2,
                              const float* __restrict__ l1b, const float* __restrict__ l2b,
                              const float* __restrict__ W30, const float* __restrict__ W31,
                              int n, int e, int nbE, int nbA) {
    if (blockIdx.x < (unsigned)nbE) {
        int i = blockIdx.x * 256 + threadIdx.x;
        if (i < e) {
            atomicAdd(&g_s.deg[src[i]], 1);
            atomicAdd(&g_s.cnt[dst[i]], 1);
        }
        return;
    }
    if (blockIdx.x < (unsigned)(nbE + nbA)) {
        int i = (blockIdx.x - nbE) * 256 + threadIdx.x;
        if (i < n * FP) {
            int r = i >> 6, f = i & 63;
            float v = (f < F_IN) ? x[(long)r * F_IN + f] : 0.f;
            g_s.xpA[(long)r * KA1 + f] = __float2half(v);
        }
        return;
    }
    int i = (blockIdx.x - nbE - nbA) * 256 + threadIdx.x;
    if (i < CN1) {
        int k = i / H1P, m = i % H1P;
        float v = 0.f;
        if (m < H1) {
            if (k < F_IN) v = W10[k * H1 + m];
            else if (k >= FP && k < FP + F_IN) v = W11[(k - FP) * H1 + m];
        }
        g_s.W1c[i] = __float2half(v);
        return;
    }
    i -= CN1;
    if (i < CN2) {
        int k = i / M2B, m = i % M2B;
        float v = 0.f;
        if (k < H1) {
            if (m < H2P) { if (m < H2) v = W21[k * H2 + m]; }
            else { int mm = m - H2P; if (mm < H2) v = W20[k * H2 + mm]; }
        }
        g_s.W2c[i] = __float2half(v);
        return;
    }
    i -= CN2;
    if (i < CN3) {
        int k = i >> 7, m = i & 127;
        float v = (k < F_IN && m < H2) ? l1W[m * F_IN + k] : 0.f;
        g_s.L1[i] = __float2half(v);
        return;
    }
    i -= CN3;
    if (i < CN3) {
        int k = i >> 7, m = i & 127;
        float v = (k < F_IN && m < H2) ? l2W[m * F_IN + k] : 0.f;
        g_s.L2[i] = __float2half(v);
        return;
    }
    i -= CN3;
    if (i < H1P) { g_s.b1p[i] = (i < H1) ? b1[i] : 0.f; return; }
    i -= H1P;
    if (i < H2P) { g_s.b2p[i] = (i < H2) ? b2[i] : 0.f; return; }
    i -= H2P;
    if (i < H2P) { g_s.l1bp[i] = (i < H2) ? l1b[i] : 0.f; return; }
    i -= H2P;
    if (i < H2P) { g_s.l2bp[i] = (i < H2) ? l2b[i] : 0.f; return; }
    i -= H2P;
    if (i < H2P) { g_s.w30p[i] = (i < H2) ? W30[i] : 0.f; return; }
    i -= H2P;
    if (i < H2P) { g_s.w31p[i] = (i < H2) ? W31[i] : 0.f; return; }
}

// scan stage 1 (+ dis folded in)
__global__ void scan1dis_kernel(const int* __restrict__ cnt, const int* __restrict__ deg,
                                int* __restrict__ rowptr, int* __restrict__ bsum,
                                float* __restrict__ dis, int n) {
    __shared__ int warp_sums[32];
    int tid = threadIdx.x;
    int i = blockIdx.x * 1024 + tid;
    if (i < n) {
        int d = deg[i];
        dis[i] = (d > 0) ? (1.0f / sqrtf((float)d)) : 0.0f;
    }
    int v = (i < n) ? cnt[i] : 0;
    int x = v;
    #pragma unroll
    for (int d = 1; d < 32; d <<= 1) {
        int y = __shfl_up_sync(0xFFFFFFFFu, x, d);
        if ((tid & 31) >= d) x += y;
    }
    if ((tid & 31) == 31) warp_sums[tid >> 5] = x;
    __syncthreads();
    if (tid < 32) {
        int y = warp_sums[tid];
        int zz = y;
        #pragma unroll
        for (int d = 1; d < 32; d <<= 1) {
            int w = __shfl_up_sync(0xFFFFFFFFu, zz, d);
            if (tid >= d) zz += w;
        }
        warp_sums[tid] = zz - y;
    }
    __syncthreads();
    int incl = x + warp_sums[tid >> 5];
    if (i < n) rowptr[i] = incl - v;
    if (tid == 1023) bsum[blockIdx.x] = incl;
}

// scan stages 2+3 merged.
__global__ void scan23_kernel(int* __restrict__ rowptr, int* __restrict__ cursor,
                              const int* __restrict__ bsum, int nb, int n) {
    __shared__ int s_off;
    int b = blockIdx.x;
    if (threadIdx.x == 0) {
        int run = 0;
        for (int j = 0; j < b; j++) run += bsum[j];
        s_off = run;
        if (b == nb - 1) rowptr[n] = run + bsum[b];
    }
    __syncthreads();
    int i = b * 1024 + threadIdx.x;
    if (i < n) {
        int v = rowptr[i] + s_off;
        rowptr[i] = v;
        cursor[i] = v;
    }
}

// fill: single packed int2 scattered store per edge.
__global__ void fill_kernel(const int* __restrict__ src, const int* __restrict__ dst,
                            const float* __restrict__ dis, int* __restrict__ cursor,
                            int2* __restrict__ csr_sn, int e) {
    int i = blockIdx.x * blockDim.x + threadIdx.x;
    if (i < e) {
        int s = src[i], d = dst[i];
        int p = atomicAdd(&cursor[d], 1);
        float w = -(dis[s] * dis[d]);
        csr_sn[p] = make_int2(s, __float_as_int(w));
    }
}

// ---------------------------------------------------------------------------
// Stage-1 aggregation over fp16 x rows -> xpA cols [64,128).
// ---------------------------------------------------------------------------
__global__ void aggx_kernel(const int2* __restrict__ csr_sn, const int* __restrict__ rowptr,
                            __half* __restrict__ xpA, int n) {
    int node = (blockIdx.x * blockDim.x + threadIdx.x) >> 5;
    int lane = threadIdx.x & 31;
    if (node >= n) return;
    int beg = rowptr[node], end = rowptr[node + 1];
    float a0 = 0.f, a1 = 0.f;
    bool act = (lane < 29);
    for (int j = beg; j < end; j++) {
        int2 sn = csr_sn[j];
        float w = __int_as_float(sn.y);
        if (act) {
            __half2 v = *reinterpret_cast<const __half2*>(xpA + (long)sn.x * KA1 + 2 * lane);
            float2 f = __half22float2(v);
            a0 += f.x * w;
            a1 += f.y * w;
        }
    }
    long o = (long)node * KA1 + FP + 2 * lane;
    *reinterpret_cast<__half2*>(xpA + o) =
        __floats2half2_rn(act ? a0 : 0.f, act ? a1 : 0.f);
}

// ---------------------------------------------------------------------------
// Shared GEMM body (double-buffered cp.async fp16 tensor-core).
// BM=128, BN=64, BK=32, 8 warps 32x32 each.
// MODE 0: Cb[r*M+c] = fp16(acc)
// MODE 1: Cb[r*M+c] = fp16(relu(acc + bias1))
// MODE 4: x1 = relu(addmh + addm2h + bias3); xm = x1 + relu(acc1 + bias1);
//         s0/s1 += xm.w3{0,1}; Z8 = fp8(x1 + relu(acc2 + bias2)), cols<100
// ---------------------------------------------------------------------------
template <int MODE, bool DUALOUT>
__device__ __forceinline__
void hgemm_body(int bm, int bn,
                const __half* __restrict__ A, int lda, int K,
                const __half* __restrict__ B1, const __half* __restrict__ B2, int ldb,
                const __half* __restrict__ addmh, const __half* __restrict__ addm2h,
                const float* __restrict__ bias1, const float* __restrict__ bias2,
                const float* __restrict__ bias3,
                const float* __restrict__ w30, const float* __restrict__ w31,
                float* __restrict__ S0, float* __restrict__ S1,
                __half* __restrict__ Cb, uint8_t* __restrict__ Z8,
                int Nr, int M) {
    __shared__ __align__(16) __half As[2][128][40];
    __shared__ __align__(16) __half Bs[2][32][72];
    __shared__ __align__(16) __half Bs2[DUALOUT ? 2 : 1][32][72];

    int tid = threadIdx.x;
    int lane = tid & 31, wid = tid >> 5;
    int wm = (wid >> 1) * 32, wn = (wid & 1) * 32;

    int a_row = tid >> 1;
    int a_seg = (tid & 1) * 2;
    int b_row = tid >> 3, b_seg = tid & 7;

    float acc[2][4][4];
    float acc2[2][4][4];
    #pragma unroll
    for (int mf = 0; mf < 2; mf++)
        #pragma unroll
        for (int nf = 0; nf < 4; nf++)
            #pragma unroll
            for (int q = 0; q < 4; q++) { acc[mf][nf][q] = 0.f; acc2[mf][nf][q] = 0.f; }

    int nIter = K >> 5;

    auto load_stage = [&](int it, int stg) {
        int k0 = it << 5;
        bool ok = (bm + a_row) < Nr;
        long aoff = (long)(bm + a_row) * lda + k0 + a_seg * 8;
        cp_async16(smem_u32(&As[stg][a_row][a_seg * 8]), A + aoff, ok);
        cp_async16(smem_u32(&As[stg][a_row][(a_seg + 1) * 8]), A + aoff + 8, ok);
        long boff = (long)(k0 + b_row) * ldb + bn + b_seg * 8;
        cp_async16(smem_u32(&Bs[stg][b_row][b_seg * 8]), B1 + boff, true);
        if constexpr (DUALOUT)
            cp_async16(smem_u32(&Bs2[stg][b_row][b_seg * 8]), B2 + boff, true);
    };

    load_stage(0, 0);
    cp_commit();

    for (int it = 0; it < nIter; it++) {
        int stg = it & 1;
        if (it > 0) __syncthreads();
        if (it + 1 < nIter) {
            load_stage(it + 1, (it + 1) & 1);
            cp_commit();
            cp_wait<1>();
        } else {
            cp_wait<0>();
        }
        __syncthreads();

        #pragma unroll
        for (int s = 0; s < 32; s += 16) {
            uint32_t a[2][4];
            #pragma unroll
            for (int mf = 0; mf < 2; mf++) {
                int row = wm + mf * 16 + (lane & 15);
                int col = s + ((lane >> 4) << 3);
                ldm_x4(a[mf], smem_u32(&As[stg][row][col]));
            }
            int kr = s + (lane & 7) + (lane & 8);
            int nshift = (lane >> 4) << 3;
            uint32_t b[4][2];
            #pragma unroll
            for (int g = 0; g < 2; g++) {
                int nc = wn + g * 16 + nshift;
                uint32_t r[4];
                ldm_x4_t(r, smem_u32(&Bs[stg][kr][nc]));
                b[g * 2][0] = r[0]; b[g * 2][1] = r[1];
                b[g * 2 + 1][0] = r[2]; b[g * 2 + 1][1] = r[3];
            }
            #pragma unroll
            for (int mf = 0; mf < 2; mf++)
                #pragma unroll
                for (int nf = 0; nf < 4; nf++)
                    mma_fp16(acc[mf][nf], a[mf], b[nf]);
            if constexpr (DUALOUT) {
                uint32_t b2[4][2];
                #pragma unroll
                for (int g = 0; g < 2; g++) {
                    int nc = wn + g * 16 + nshift;
                    uint32_t r[4];
                    ldm_x4_t(r, smem_u32(&Bs2[stg][kr][nc]));
                    b2[g * 2][0] = r[0]; b2[g * 2][1] = r[1];
                    b2[g * 2 + 1][0] = r[2]; b2[g * 2 + 1][1] = r[3];
                }
                #pragma unroll
                for (int mf = 0; mf < 2; mf++)
                    #pragma unroll
                    for (int nf = 0; nf < 4; nf++)
                        mma_fp16(acc2[mf][nf], a[mf], b2[nf]);
            }
        }
    }

    // --- epilogue
    int gid = lane >> 2, tig = lane & 3;
    if constexpr (MODE == 4) {
        #pragma unroll
        for (int mf = 0; mf < 2; mf++) {
            #pragma unroll
            for (int half_i = 0; half_i < 2; half_i++) {
                int r = bm + wm + mf * 16 + gid + half_i * 8;
                bool valid = (r < Nr);
                float p0 = 0.f, p1 = 0.f;
                #pragma unroll
                for (int nf = 0; nf < 4; nf++) {
                    int c = bn + wn + nf * 8 + tig * 2;
                    if (valid) {
                        long base = (long)r * H2P + c;
                        float ah0 = __half2float(addmh[base]);
                        float ah1 = __half2float(addmh[base + 1]);
                        float g0 = __half2float(addm2h[base]);
                        float g1 = __half2float(addm2h[base + 1]);
                        float x10 = fmaxf(ah0 + g0 + bias3[c],     0.f);
                        float x11 = fmaxf(ah1 + g1 + bias3[c + 1], 0.f);
                        float xm0 = x10 + fmaxf(acc[mf][nf][half_i * 2 + 0] + bias1[c],     0.f);
                        float xm1 = x11 + fmaxf(acc[mf][nf][half_i * 2 + 1] + bias1[c + 1], 0.f);
                        p0 += xm0 * w30[c] + xm1 * w30[c + 1];
                        p1 += xm0 * w31[c] + xm1 * w31[c + 1];
                        if (c < ZSB) {
                            float z0 = 0.f, z1 = 0.f;
                            if (c < H2) {
                                z0 = x10 + fmaxf(acc2[mf][nf][half_i * 2 + 0] + bias2[c],     0.f);
                                z1 = x11 + fmaxf(acc2[mf][nf][half_i * 2 + 1] + bias2[c + 1], 0.f);
                            }
                            __nv_fp8x2_storage_t pk = __nv_cvt_float2_to_fp8x2(
                                make_float2(z0, z1), __NV_SATFINITE, __NV_E4M3);
                            *reinterpret_cast<unsigned short*>(Z8 + (long)r * ZSB + c) = pk;
                        }
                    }
                }
                p0 += __shfl_down_sync(0xFFFFFFFFu, p0, 1);
                p0 += __shfl_down_sync(0xFFFFFFFFu, p0, 2);
                p1 += __shfl_down_sync(0xFFFFFFFFu, p1, 1);
                p1 += __shfl_down_sync(0xFFFFFFFFu, p1, 2);
                if (tig == 0 && valid) {
                    atomicAdd(&S0[r], p0);
                    atomicAdd(&S1[r], p1);
                }
            }
        }
    } else {
        #pragma unroll
        for (int mf = 0; mf < 2; mf++) {
            #pragma unroll
            for (int nf = 0; nf < 4; nf++) {
                int c = bn + wn + nf * 8 + tig * 2;
                float bv0 = 0.f, bv1 = 0.f;
                if constexpr (MODE == 1) { bv0 = bias1[c]; bv1 = bias1[c + 1]; }
                #pragma unroll
                for (int half_i = 0; half_i < 2; half_i++) {
                    int r = bm + wm + mf * 16 + gid + half_i * 8;
                    if (r >= Nr) continue;
                    float v0 = acc[mf][nf][half_i * 2 + 0];
                    float v1 = acc[mf][nf][half_i * 2 + 1];
                    if constexpr (MODE == 1) {
                        v0 = fmaxf(v0 + bv0, 0.f);
                        v1 = fmaxf(v1 + bv1, 0.f);
                    }
                    long base = (long)r * M + c;
                    Cb[base]     = __float2half(v0);
                    Cb[base + 1] = __float2half(v1);
                }
            }
        }
    }
}

// --- standalone GEMM wrappers ---
__global__ __launch_bounds__(256)
void g1_kernel(const __half* A, const __half* B1, const float* bias1,
               __half* Cb, int Nr) {
    hgemm_body<1, false>(blockIdx.y * 128, blockIdx.x * 64, A, KA1, KA1,
                         B1, nullptr, H1P, nullptr, nullptr, bias1, nullptr, nullptr,
                         nullptr, nullptr, nullptr, nullptr, Cb, nullptr, Nr, H1P);
}
__global__ __launch_bounds__(256)
void g2a_kernel(const __half* A, const __half* B1, __half* Cb, int Nr) {
    hgemm_body<0, false>(blockIdx.y * 128, blockIdx.x * 64, A, KH, KH,
                         B1, nullptr, M2B, nullptr, nullptr, nullptr, nullptr, nullptr,
                         nullptr, nullptr, nullptr, nullptr, Cb, nullptr, Nr, H2P);
}
__global__ __launch_bounds__(256)
void g4_kernel(const __half* A, const __half* B1, const __half* B2,
               const __half* addmh, const __half* addm2h,
               const float* bias1, const float* bias2, const float* bias3,
               const float* w30, const float* w31,
               float* S0, float* S1, uint8_t* Z8, int Nr) {
    hgemm_body<4, true>(blockIdx.y * 128, blockIdx.x * 64, A, KA1, FP,
                        B1, B2, H2P, addmh, addm2h, bias1, bias2, bias3,
                        w30, w31, S0, S1, nullptr, Z8, Nr, H2P);
}

// ---------------------------------------------------------------------------
// Merged: G2b (W2_0 half) blocks [0,gB) ∥ agg2h blocks [gB,..).
// agg2h reads hW21f (written by the PRIOR G2a launch); G2b writes hW20h.
// agg2 stored fp16.
// ---------------------------------------------------------------------------
__global__ __launch_bounds__(256)
void g2b_agg2_kernel(const __half* __restrict__ h_fp, const __half* __restrict__ B20,
                     __half* __restrict__ hW20h,
                     const __half* __restrict__ hW21f, const int2* __restrict__ csr_sn,
                     const int* __restrict__ rowptr, __half* __restrict__ agg2,
                     int n, int gB) {
    if (blockIdx.x < (unsigned)gB) {
        int bid = blockIdx.x;
        int bn = (bid & 1) * 64;
        int bm = (bid >> 1) * 128;
        hgemm_body<0, false>(bm, bn, h_fp, KH, KH, B20, nullptr, M2B,
                             nullptr, nullptr, nullptr, nullptr, nullptr,
                             nullptr, nullptr, nullptr, nullptr, hW20h, nullptr, n, H2P);
        return;
    }
    int node = ((int)(blockIdx.x - gB) * 256 + threadIdx.x) >> 5;
    int lane = threadIdx.x & 31;
    if (node >= n) return;
    int beg = rowptr[node], end = rowptr[node + 1];
    float a0 = 0.f, a1 = 0.f, a2 = 0.f, a3 = 0.f;
    bool act2 = (lane < 18);
    for (int j = beg; j < end; j++) {
        int2 sn = csr_sn[j];
        float w = __int_as_float(sn.y);
        const __half2* vr = reinterpret_cast<const __half2*>(hW21f + (long)sn.x * H2P);
        float2 f0 = __half22float2(vr[lane]);
        a0 += f0.x * w; a1 += f0.y * w;
        if (act2) {
            float2 f1 = __half22float2(vr[32 + lane]);
            a2 += f1.x * w; a3 += f1.y * w;
        }
    }
    __half2* orow = reinterpret_cast<__half2*>(agg2 + (long)node * H2P);
    orow[lane]      = __floats2half2_rn(a0, a1);
    orow[32 + lane] = __floats2half2_rn(act2 ? a2 : 0.f, act2 ? a3 : 0.f);
}

// ---------------------------------------------------------------------------
// Merged score + agg1 + final (done-counter). Score over fp8 z: 8 lanes/edge.
// ---------------------------------------------------------------------------
#define SB 2048
__global__ void score_agg1_kernel(const uint8_t* __restrict__ z8, const int* __restrict__ ei,
                                  const int* __restrict__ nei, int E_, float* __restrict__ accum,
                                  const float* __restrict__ s0, const float* __restrict__ s1,
                                  const int2* __restrict__ csr_sn,
                                  const int* __restrict__ rowptr, const float* __restrict__ b3,
                                  const float* __restrict__ c1, const float* __restrict__ c2,
                                  float* __restrict__ out, int n, float invE,
                                  int* __restrict__ done) {
    if (blockIdx.x >= SB) {
        int i = (blockIdx.x - SB) * 256 + threadIdx.x;
        if (i < n) {
            float a = 0.f;
            int end = rowptr[i + 1];
            for (int j = rowptr[i]; j < end; j++) {
                int2 sn = csr_sn[j];
                a += s1[sn.x] * __int_as_float(sn.y);
            }
            out[i] = s0[i] + a + b3[0];
        }
    } else {
        int lane = threadIdx.x & 31;
        int grp = lane >> 3;
        int l = lane & 7;
        int warp_global = (blockIdx.x * blockDim.x + threadIdx.x) >> 5;
        int nwarps = (SB * 256) >> 5;
        int total = 2 * E_;
        float psum = 0.f, nsum = 0.f;
        for (int t0 = warp_global * 4; t0 < total; t0 += nwarps * 4) {
            int t = t0 + grp;
            float dot = 0.f;
            int which = 0;
            if (t < total) {
                which = (t >= E_);
                const int* p = which ? nei : ei;
                int e = which ? t - E_ : t;
                int a = p[e], b = p[e + E_];
                if (l < 7) {
                    uint4 ua = *reinterpret_cast<const uint4*>(z8 + (long)a * ZSB + l * 16);
                    uint4 ub = *reinterpret_cast<const uint4*>(z8 + (long)b * ZSB + l * 16);
                    const __nv_fp8x2_storage_t* pa =
                        reinterpret_cast<const __nv_fp8x2_storage_t*>(&ua);
                    const __nv_fp8x2_storage_t* pb =
                        reinterpret_cast<const __nv_fp8x2_storage_t*>(&ub);
                    #pragma unroll
                    for (int q = 0; q < 8; q++) {
                        __half2_raw ra = __nv_cvt_fp8x2_to_halfraw2(pa[q], __NV_E4M3);
                        __half2_raw rb = __nv_cvt_fp8x2_to_halfraw2(pb[q], __NV_E4M3);
                        float2 fa = __half22float2(*reinterpret_cast<__half2*>(&ra));
                        float2 fb = __half22float2(*reinterpret_cast<__half2*>(&rb));
                        dot += fa.x * fb.x + fa.y * fb.y;
                    }
                }
            }
            dot += __shfl_down_sync(0xFFFFFFFFu, dot, 4);
            dot += __shfl_down_sync(0xFFFFFFFFu, dot, 2);
            dot += __shfl_down_sync(0xFFFFFFFFu, dot, 1);
            if (l == 0 && t < total) {
                float sig = 1.f / (1.f + expf(-dot));
                if (which) nsum += logf(1.f - sig + 1e-15f);
                else       psum += logf(sig + 1e-15f);
            }
        }
        psum += __shfl_down_sync(0xFFFFFFFFu, psum, 16);
        psum += __shfl_down_sync(0xFFFFFFFFu, psum, 8);
        nsum += __shfl_down_sync(0xFFFFFFFFu, nsum, 16);
        nsum += __shfl_down_sync(0xFFFFFFFFu, nsum, 8);
        __shared__ float redp[32], redn[32];
        if (lane == 0) { redp[threadIdx.x >> 5] = psum; redn[threadIdx.x >> 5] = nsum; }
        __syncthreads();
        if (threadIdx.x < 32) {
            int nw = blockDim.x >> 5;
            float vp = (threadIdx.x < nw) ? redp[threadIdx.x] : 0.f;
            float vn = (threadIdx.x < nw) ? redn[threadIdx.x] : 0.f;
            #pragma unroll
            for (int dd = 16; dd; dd >>= 1) {
                vp += __shfl_down_sync(0xFFFFFFFFu, vp, dd);
                vn += __shfl_down_sync(0xFFFFFFFFu, vn, dd);
            }
            if (threadIdx.x == 0) {
                atomicAdd(&accum[0], vp);
                atomicAdd(&accum[1], vn);
            }
        }
    }
    // final: last block to finish writes out[n..n+2]
    __syncthreads();
    if (threadIdx.x == 0) {
        __threadfence();
        int prev = atomicAdd(done, 1);
        if (prev == (int)gridDim.x - 1) {
            out[n] = -(accum[0] + accum[1]) * invE;
            out[n + 1] = c1[0];
            out[n + 2] = c2[0];
        }
    }
}

// ---------------------------------------------------------------------------
// Launch
// ---------------------------------------------------------------------------
extern "C" void kernel_launch(void* const* d_in, const int* in_sizes, int n_in,
                              void* d_out, int out_size) {
    const float* x      = (const float*)d_in[0];
    const int*   ei     = (const int*)d_in[1];
    const int*   nei    = (const int*)d_in[2];
    const float* W1_0   = (const float*)d_in[3];
    const float* W1_1   = (const float*)d_in[4];
    const float* b1     = (const float*)d_in[5];
    const float* W2_0   = (const float*)d_in[6];
    const float* W2_1   = (const float*)d_in[7];
    const float* b2     = (const float*)d_in[8];
    const float* W3_0   = (const float*)d_in[9];
    const float* W3_1   = (const float*)d_in[10];
    const float* b3     = (const float*)d_in[11];
    const float* lin1_W = (const float*)d_in[12];
    const float* lin1_b = (const float*)d_in[13];
    const float* lin2_W = (const float*)d_in[14];
    const float* lin2_b = (const float*)d_in[15];
    const float* c1     = (const float*)d_in[16];
    const float* c2     = (const float*)d_in[17];
    float* out = (float*)d_out;

    int n = in_sizes[0] / F_IN;   // 50000
    int e = in_sizes[1] / 2;      // 800000

    Scratch* sp = nullptr;
    cudaGetSymbolAddress((void**)&sp, g_s);

    const int* src = ei;
    const int* dst = ei + e;

    int nb_n = (n + 255) / 256;
    int nb_e = (e + 255) / 256;
    int agg_blocks = (n * 32 + 255) / 256;
    int nb_scan = (n + 1023) / 1024;
    int gy = (n + 127) / 128;
    int nbA = (n * FP + 255) / 256;
    int nbC = (CTOT + 255) / 256;

    // 1. zero (ordering anchor)
    zero_kernel<<<nb_n, 256>>>(n);

    // 2. setup2: hist ∥ pad-x ∥ weight conv
    setup2_kernel<<<nb_e + nbA + nbC, 256>>>(x, src, dst, W1_0, W1_1, W2_0, W2_1,
                                             lin1_W, lin2_W, b1, b2, lin1_b, lin2_b,
                                             W3_0, W3_1, n, e, nb_e, nbA);

    // 3-5. CSR build
    scan1dis_kernel<<<nb_scan, 1024>>>(sp->cnt, sp->deg, sp->rowptr, sp->bsum, sp->dis, n);
    scan23_kernel<<<nb_scan, 1024>>>(sp->rowptr, sp->cursor, sp->bsum, nb_scan, n);
    fill_kernel<<<nb_e, 256>>>(src, dst, sp->dis, sp->cursor, sp->csr_sn, e);

    // 6. Stage 1 aggregation -> xpA cols [64,128)
    aggx_kernel<<<agg_blocks, 256>>>(sp->csr_sn, sp->rowptr, sp->xpA, n);

    // 7. G1: h(fp16) = relu([xp|tx1] @ W1cat + b1)   K=128, M=320
    g1_kernel<<<dim3(H1P / 64, gy), 256>>>(sp->xpA, sp->W1c, sp->b1p, sp->h_fp, n);

    // 8. G2a: hW21f = fp16(h @ W2_1)   K=320, M=128 (ldb=256)
    g2a_kernel<<<dim3(H2P / 64, gy), 256>>>(sp->h_fp, sp->W2c, sp->hW21f, n);

    // 9. merged: G2b (hW20h = fp16(h @ W2_0)) ∥ agg2 = Agg(hW21f)
    int gB = (H2P / 64) * gy;
    g2b_agg2_kernel<<<gB + agg_blocks, 256>>>(sp->h_fp, sp->W2c + H2P, sp->hW20h,
                                              sp->hW21f, sp->csr_sn, sp->rowptr,
                                              sp->agg2h, n, gB);

    // 10. G4: s0/s1 += xm.W3; z8 = fp8(z); x1 = relu(hW20h + agg2 + b2) inline
    g4_kernel<<<dim3(H2P / 64, gy), 256>>>(sp->xpA, sp->L1, sp->L2, sp->hW20h, sp->agg2h,
                                           sp->l1bp, sp->l2bp, sp->b2p, sp->w30p, sp->w31p,
                                           sp->s0, sp->s1, sp->z8, n);

    // 11. score + agg1 + final (done-counter)
    score_agg1_kernel<<<SB + nb_n, 256>>>(sp->z8, ei, nei, e, sp->accum,
                                          sp->s0, sp->s1, sp->csr_sn, sp->rowptr,
                                          b3, c1, c2, out, n, 1.0f / (float)e, sp->done);
}

// round 15
// speedup vs baseline: 1.0527x; 1.0527x over previous
#include <cuda_runtime.h>
#include <cuda_fp16.h>
#include <cuda_fp8.h>
#include <cstdint>
#include <math.h>

#define NN 50000
#define EE 800000
#define F_IN 58
#define FP 64
#define H1 300
#define H2 100
#define H1P 320
#define H2P 128
#define KA1 128   // GEMM1 K: [xp|tx1]
#define KH 320    // padded K for fused stage-2 GEMM
#define M2B 256   // fused stage-2 GEMM logical N: [W2_1|W2_0]
#define ZSB 112   // z row stride in BYTES (fp8); cols 100..111 == 0

// ---------------------------------------------------------------------------
// Scratch (device-global, no runtime allocation).
// ---------------------------------------------------------------------------
struct alignas(16) Scratch {
    int   deg[NN];
    int   cnt[NN];
    int   rowptr[NN + 4];
    int   cursor[NN];
    int2  csr_sn[EE];        // packed (src, norm-bits) in CSR(dst) order
    int   bsum[64];
    float dis[NN];
    __half xpA[NN * KA1];    // [x_fp16 | Agg(x)] fp16
    __half h_fp[NN * KH];    // relu(cheb1) fp16, [N,320]
    __half hW21f[NN * H2P];  // h @ W2_1 (fp16, gathered by agg2)
    __half hW20h[NN * H2P];  // h @ W2_0 (fp16)
    __half agg2h[NN * H2P];  // Agg(hW21f) fp16
    uint8_t z8[NN * ZSB];    // compact fp8(e4m3) z
    __half W1c[KA1 * H1P];   // [128,320]
    __half W2c[KH * M2B];    // [320,256]
    __half L1[FP * H2P];     // [64,128]
    __half L2[FP * H2P];
    float b1p[H1P], b2p[H2P], l1bp[H2P], l2bp[H2P];
    float w30p[H2P], w31p[H2P];
    float s0[NN], s1[NN];
    float accum[2];
};
__device__ Scratch g_s;

// ---------------------------------------------------------------------------
// PTX helpers
// ---------------------------------------------------------------------------
__device__ __forceinline__ uint32_t smem_u32(const void* p) {
    return (uint32_t)__cvta_generic_to_shared(p);
}
__device__ __forceinline__ void ldm_x4(uint32_t* r, uint32_t addr) {
    asm volatile("ldmatrix.sync.aligned.m8n8.x4.shared.b16 {%0,%1,%2,%3}, [%4];"
                 : "=r"(r[0]), "=r"(r[1]), "=r"(r[2]), "=r"(r[3]) : "r"(addr));
}
__device__ __forceinline__ void ldm_x4_t(uint32_t* r, uint32_t addr) {
    asm volatile("ldmatrix.sync.aligned.m8n8.x4.trans.shared.b16 {%0,%1,%2,%3}, [%4];"
                 : "=r"(r[0]), "=r"(r[1]), "=r"(r[2]), "=r"(r[3]) : "r"(addr));
}
__device__ __forceinline__ void mma_fp16(float* c, const uint32_t* a, const uint32_t* b) {
    asm volatile("mma.sync.aligned.m16n8k16.row.col.f32.f16.f16.f32 "
                 "{%0,%1,%2,%3}, {%4,%5,%6,%7}, {%8,%9}, {%0,%1,%2,%3};"
                 : "+f"(c[0]), "+f"(c[1]), "+f"(c[2]), "+f"(c[3])
                 : "r"(a[0]), "r"(a[1]), "r"(a[2]), "r"(a[3]), "r"(b[0]), "r"(b[1]));
}
__device__ __forceinline__ void cp_async16(uint32_t dst, const void* src, bool pred) {
    int sz = pred ? 16 : 0;
    asm volatile("cp.async.cg.shared.global [%0], [%1], 16, %2;\n"
                 :: "r"(dst), "l"(src), "r"(sz));
}
__device__ __forceinline__ void cp_commit() {
    asm volatile("cp.async.commit_group;\n");
}
template <int N>
__device__ __forceinline__ void cp_wait() {
    asm volatile("cp.async.wait_group %0;\n" :: "n"(N));
}

// ---------------------------------------------------------------------------
// Fused setup (race-free): zero/pad-x in blocks [0,nbA); weight conversions
// in blocks [nbA,..). Histogram runs in a LATER kernel.
// ---------------------------------------------------------------------------
#define CN1 (KA1 * H1P)
#define CN2 (KH * M2B)
#define CN3 (FP * H2P)
#define CTOT (CN1 + CN2 + 2 * CN3 + H1P + 5 * H2P)
__global__ void setup_kernel(const float* __restrict__ x,
                             const float* __restrict__ W10, const float* __restrict__ W11,
                             const float* __restrict__ W20, const float* __restrict__ W21,
                             const float* __restrict__ l1W, const float* __restrict__ l2W,
                             const float* __restrict__ b1, const float* __restrict__ b2,
                             const float* __restrict__ l1b, const float* __restrict__ l2b,
                             const float* __restrict__ W30, const float* __restrict__ W31,
                             int n, int nbA) {
    if (blockIdx.x < (unsigned)nbA) {
        int i = blockIdx.x * 256 + threadIdx.x;
        if (i < n) { g_s.deg[i] = 0; g_s.cnt[i] = 0; g_s.s0[i] = 0.f; g_s.s1[i] = 0.f; }
        if (i < 2) g_s.accum[i] = 0.f;
        if (i < n * FP) {
            int r = i >> 6, f = i & 63;
            float v = (f < F_IN) ? x[(long)r * F_IN + f] : 0.f;
            g_s.xpA[(long)r * KA1 + f] = __float2half(v);
        }
        return;
    }
    int i = (blockIdx.x - nbA) * 256 + threadIdx.x;
    if (i < CN1) {
        int k = i / H1P, m = i % H1P;
        float v = 0.f;
        if (m < H1) {
            if (k < F_IN) v = W10[k * H1 + m];
            else if (k >= FP && k < FP + F_IN) v = W11[(k - FP) * H1 + m];
        }
        g_s.W1c[i] = __float2half(v);
        return;
    }
    i -= CN1;
    if (i < CN2) {
        int k = i / M2B, m = i % M2B;
        float v = 0.f;
        if (k < H1) {
            if (m < H2P) { if (m < H2) v = W21[k * H2 + m]; }
            else { int mm = m - H2P; if (mm < H2) v = W20[k * H2 + mm]; }
        }
        g_s.W2c[i] = __float2half(v);
        return;
    }
    i -= CN2;
    if (i < CN3) {
        int k = i >> 7, m = i & 127;
        float v = (k < F_IN && m < H2) ? l1W[m * F_IN + k] : 0.f;
        g_s.L1[i] = __float2half(v);
        return;
    }
    i -= CN3;
    if (i < CN3) {
        int k = i >> 7, m = i & 127;
        float v = (k < F_IN && m < H2) ? l2W[m * F_IN + k] : 0.f;
        g_s.L2[i] = __float2half(v);
        return;
    }
    i -= CN3;
    if (i < H1P) { g_s.b1p[i] = (i < H1) ? b1[i] : 0.f; return; }
    i -= H1P;
    if (i < H2P) { g_s.b2p[i] = (i < H2) ? b2[i] : 0.f; return; }
    i -= H2P;
    if (i < H2P) { g_s.l1bp[i] = (i < H2) ? l1b[i] : 0.f; return; }
    i -= H2P;
    if (i < H2P) { g_s.l2bp[i] = (i < H2) ? l2b[i] : 0.f; return; }
    i -= H2P;
    if (i < H2P) { g_s.w30p[i] = (i < H2) ? W30[i] : 0.f; return; }
    i -= H2P;
    if (i < H2P) { g_s.w31p[i] = (i < H2) ? W31[i] : 0.f; return; }
}

// Histogram — strictly after setup_kernel.
__global__ void hist_kernel(const int* __restrict__ src, const int* __restrict__ dst,
                            int* deg, int* cnt, int e) {
    int i = blockIdx.x * blockDim.x + threadIdx.x;
    if (i < e) {
        atomicAdd(&deg[src[i]], 1);
        atomicAdd(&cnt[dst[i]], 1);
    }
}

// scan stage 1 (+ dis folded in)
__global__ void scan1dis_kernel(const int* __restrict__ cnt, const int* __restrict__ deg,
                                int* __restrict__ rowptr, int* __restrict__ bsum,
                                float* __restrict__ dis, int n) {
    __shared__ int warp_sums[32];
    int tid = threadIdx.x;
    int i = blockIdx.x * 1024 + tid;
    if (i < n) {
        int d = deg[i];
        dis[i] = (d > 0) ? (1.0f / sqrtf((float)d)) : 0.0f;
    }
    int v = (i < n) ? cnt[i] : 0;
    int x = v;
    #pragma unroll
    for (int d = 1; d < 32; d <<= 1) {
        int y = __shfl_up_sync(0xFFFFFFFFu, x, d);
        if ((tid & 31) >= d) x += y;
    }
    if ((tid & 31) == 31) warp_sums[tid >> 5] = x;
    __syncthreads();
    if (tid < 32) {
        int y = warp_sums[tid];
        int zz = y;
        #pragma unroll
        for (int d = 1; d < 32; d <<= 1) {
            int w = __shfl_up_sync(0xFFFFFFFFu, zz, d);
            if (tid >= d) zz += w;
        }
        warp_sums[tid] = zz - y;
    }
    __syncthreads();
    int incl = x + warp_sums[tid >> 5];
    if (i < n) rowptr[i] = incl - v;
    if (tid == 1023) bsum[blockIdx.x] = incl;
}

// scan stages 2+3 merged.
__global__ void scan23_kernel(int* __restrict__ rowptr, int* __restrict__ cursor,
                              const int* __restrict__ bsum, int nb, int n) {
    __shared__ int s_off;
    int b = blockIdx.x;
    if (threadIdx.x == 0) {
        int run = 0;
        for (int j = 0; j < b; j++) run += bsum[j];
        s_off = run;
        if (b == nb - 1) rowptr[n] = run + bsum[b];
    }
    __syncthreads();
    int i = b * 1024 + threadIdx.x;
    if (i < n) {
        int v = rowptr[i] + s_off;
        rowptr[i] = v;
        cursor[i] = v;
    }
}

// fill: single packed int2 scattered store per edge.
__global__ void fill_kernel(const int* __restrict__ src, const int* __restrict__ dst,
                            const float* __restrict__ dis, int* __restrict__ cursor,
                            int2* __restrict__ csr_sn, int e) {
    int i = blockIdx.x * blockDim.x + threadIdx.x;
    if (i < e) {
        int s = src[i], d = dst[i];
        int p = atomicAdd(&cursor[d], 1);
        float w = -(dis[s] * dis[d]);
        csr_sn[p] = make_int2(s, __float_as_int(w));
    }
}

// ---------------------------------------------------------------------------
// Stage-1 aggregation over fp16 x rows (cols [0,58) of xpA) -> xpA cols [64,128).
// ---------------------------------------------------------------------------
__global__ void aggx_kernel(const int2* __restrict__ csr_sn, const int* __restrict__ rowptr,
                            __half* __restrict__ xpA, int n) {
    int node = (blockIdx.x * blockDim.x + threadIdx.x) >> 5;
    int lane = threadIdx.x & 31;
    if (node >= n) return;
    int beg = rowptr[node], end = rowptr[node + 1];
    float a0 = 0.f, a1 = 0.f;
    bool act = (lane < 29);
    for (int j = beg; j < end; j++) {
        int2 sn = csr_sn[j];
        float w = __int_as_float(sn.y);
        if (act) {
            __half2 v = *reinterpret_cast<const __half2*>(xpA + (long)sn.x * KA1 + 2 * lane);
            float2 f = __half22float2(v);
            a0 += f.x * w;
            a1 += f.y * w;
        }
    }
    long o = (long)node * KA1 + FP + 2 * lane;
    *reinterpret_cast<__half2*>(xpA + o) =
        __floats2half2_rn(act ? a0 : 0.f, act ? a1 : 0.f);
}

// ---------------------------------------------------------------------------
// agg2 over fp16 rows [N,128], live cols [0,100): out fp16 [N,128].
// ---------------------------------------------------------------------------
__global__ void agg2h_kernel(const __half* __restrict__ val, const int2* __restrict__ csr_sn,
                             const int* __restrict__ rowptr, __half* __restrict__ out, int n) {
    int node = (blockIdx.x * blockDim.x + threadIdx.x) >> 5;
    int lane = threadIdx.x & 31;
    if (node >= n) return;
    int beg = rowptr[node], end = rowptr[node + 1];
    float a0 = 0.f, a1 = 0.f, a2 = 0.f, a3 = 0.f;
    bool act2 = (lane < 18);
    for (int j = beg; j < end; j++) {
        int2 sn = csr_sn[j];
        float w = __int_as_float(sn.y);
        const __half2* vr = reinterpret_cast<const __half2*>(val + (long)sn.x * H2P);
        float2 f0 = __half22float2(vr[lane]);
        a0 += f0.x * w; a1 += f0.y * w;
        if (act2) {
            float2 f1 = __half22float2(vr[32 + lane]);
            a2 += f1.x * w; a3 += f1.y * w;
        }
    }
    __half2* orow = reinterpret_cast<__half2*>(out + (long)node * H2P);
    orow[lane]      = __floats2half2_rn(a0, a1);
    orow[32 + lane] = __floats2half2_rn(act2 ? a2 : 0.f, act2 ? a3 : 0.f);
}

// ---------------------------------------------------------------------------
// Double-buffered (cp.async) fp16 tensor-core GEMM.
// MODE 1: Cb = fp16(relu(acc + bias1)), stride M
// MODE 4: x1 = relu(addmh + addm2h + bias3)
//         xm = x1 + relu(acc1 + bias1); s0 += xm.w30, s1 += xm.w31 (atomic)
//         Z8 = fp8(x1 + relu(acc2 + bias2)) at byte stride ZSB, cols < 100
// MODE 5: c<128 -> Cb[r*128+c] = fp16(acc); else Cb2[r*128+(c-128)] = fp16(acc)
// ---------------------------------------------------------------------------
template <int MODE, bool DUALOUT>
__global__ __launch_bounds__(256)
void hgemm_kernel(const __half* __restrict__ A, int lda, int K,
                  const __half* __restrict__ B1, const __half* __restrict__ B2,
                  const __half* __restrict__ addmh, const __half* __restrict__ addm2h,
                  const float* __restrict__ bias1, const float* __restrict__ bias2,
                  const float* __restrict__ bias3,
                  const float* __restrict__ w30, const float* __restrict__ w31,
                  float* __restrict__ S0, float* __restrict__ S1,
                  __half* __restrict__ Cb, __half* __restrict__ Cb2,
                  uint8_t* __restrict__ Z8,
                  int Nr, int M) {
    __shared__ __align__(16) __half As[2][128][40];
    __shared__ __align__(16) __half Bs[2][32][72];
    __shared__ __align__(16) __half Bs2[DUALOUT ? 2 : 1][32][72];

    int tid = threadIdx.x;
    int bm = blockIdx.y * 128, bn = blockIdx.x * 64;
    int lane = tid & 31, wid = tid >> 5;
    int wm = (wid >> 1) * 32, wn = (wid & 1) * 32;

    int a_row = tid >> 1;
    int a_seg = (tid & 1) * 2;
    int b_row = tid >> 3, b_seg = tid & 7;

    float acc[2][4][4];
    float acc2[2][4][4];
    #pragma unroll
    for (int mf = 0; mf < 2; mf++)
        #pragma unroll
        for (int nf = 0; nf < 4; nf++)
            #pragma unroll
            for (int q = 0; q < 4; q++) { acc[mf][nf][q] = 0.f; acc2[mf][nf][q] = 0.f; }

    int nIter = K >> 5;

    auto load_stage = [&](int it, int stg) {
        int k0 = it << 5;
        bool ok = (bm + a_row) < Nr;
        long aoff = (long)(bm + a_row) * lda + k0 + a_seg * 8;
        cp_async16(smem_u32(&As[stg][a_row][a_seg * 8]), A + aoff, ok);
        cp_async16(smem_u32(&As[stg][a_row][(a_seg + 1) * 8]), A + aoff + 8, ok);
        long boff = (long)(k0 + b_row) * M + bn + b_seg * 8;
        cp_async16(smem_u32(&Bs[stg][b_row][b_seg * 8]), B1 + boff, true);
        if constexpr (DUALOUT)
            cp_async16(smem_u32(&Bs2[stg][b_row][b_seg * 8]), B2 + boff, true);
    };

    load_stage(0, 0);
    cp_commit();

    for (int it = 0; it < nIter; it++) {
        int stg = it & 1;
        if (it > 0) __syncthreads();
        if (it + 1 < nIter) {
            load_stage(it + 1, (it + 1) & 1);
            cp_commit();
            cp_wait<1>();
        } else {
            cp_wait<0>();
        }
        __syncthreads();

        #pragma unroll
        for (int s = 0; s < 32; s += 16) {
            uint32_t a[2][4];
            #pragma unroll
            for (int mf = 0; mf < 2; mf++) {
                int row = wm + mf * 16 + (lane & 15);
                int col = s + ((lane >> 4) << 3);
                ldm_x4(a[mf], smem_u32(&As[stg][row][col]));
            }
            int kr = s + (lane & 7) + (lane & 8);
            int nshift = (lane >> 4) << 3;
            uint32_t b[4][2];
            #pragma unroll
            for (int g = 0; g < 2; g++) {
                int nc = wn + g * 16 + nshift;
                uint32_t r[4];
                ldm_x4_t(r, smem_u32(&Bs[stg][kr][nc]));
                b[g * 2][0] = r[0]; b[g * 2][1] = r[1];
                b[g * 2 + 1][0] = r[2]; b[g * 2 + 1][1] = r[3];
            }
            #pragma unroll
            for (int mf = 0; mf < 2; mf++)
                #pragma unroll
                for (int nf = 0; nf < 4; nf++)
                    mma_fp16(acc[mf][nf], a[mf], b[nf]);
            if constexpr (DUALOUT) {
                uint32_t b2[4][2];
                #pragma unroll
                for (int g = 0; g < 2; g++) {
                    int nc = wn + g * 16 + nshift;
                    uint32_t r[4];
                    ldm_x4_t(r, smem_u32(&Bs2[stg][kr][nc]));
                    b2[g * 2][0] = r[0]; b2[g * 2][1] = r[1];
                    b2[g * 2 + 1][0] = r[2]; b2[g * 2 + 1][1] = r[3];
                }
                #pragma unroll
                for (int mf = 0; mf < 2; mf++)
                    #pragma unroll
                    for (int nf = 0; nf < 4; nf++)
                        mma_fp16(acc2[mf][nf], a[mf], b2[nf]);
            }
        }
    }

    // --- epilogue
    int gid = lane >> 2, tig = lane & 3;
    if constexpr (MODE == 4) {
        #pragma unroll
        for (int mf = 0; mf < 2; mf++) {
            #pragma unroll
            for (int half_i = 0; half_i < 2; half_i++) {
                int r = bm + wm + mf * 16 + gid + half_i * 8;
                bool valid = (r < Nr);
                float p0 = 0.f, p1 = 0.f;
                #pragma unroll
                for (int nf = 0; nf < 4; nf++) {
                    int c = bn + wn + nf * 8 + tig * 2;
                    if (valid) {
                        long base = (long)r * H2P + c;
                        float ah0 = __half2float(addmh[base]);
                        float ah1 = __half2float(addmh[base + 1]);
                        float g0 = __half2float(addm2h[base]);
                        float g1 = __half2float(addm2h[base + 1]);
                        float x10 = fmaxf(ah0 + g0 + bias3[c],     0.f);
                        float x11 = fmaxf(ah1 + g1 + bias3[c + 1], 0.f);
                        float xm0 = x10 + fmaxf(acc[mf][nf][half_i * 2 + 0] + bias1[c],     0.f);
                        float xm1 = x11 + fmaxf(acc[mf][nf][half_i * 2 + 1] + bias1[c + 1], 0.f);
                        p0 += xm0 * w30[c] + xm1 * w30[c + 1];
                        p1 += xm0 * w31[c] + xm1 * w31[c + 1];
                        if (c < ZSB) {
                            float z0 = 0.f, z1 = 0.f;
                            if (c < H2) {
                                z0 = x10 + fmaxf(acc2[mf][nf][half_i * 2 + 0] + bias2[c],     0.f);
                                z1 = x11 + fmaxf(acc2[mf][nf][half_i * 2 + 1] + bias2[c + 1], 0.f);
                            }
                            __nv_fp8x2_storage_t pk = __nv_cvt_float2_to_fp8x2(
                                make_float2(z0, z1), __NV_SATFINITE, __NV_E4M3);
                            *reinterpret_cast<unsigned short*>(Z8 + (long)r * ZSB + c) = pk;
                        }
                    }
                }
                p0 += __shfl_down_sync(0xFFFFFFFFu, p0, 1);
                p0 += __shfl_down_sync(0xFFFFFFFFu, p0, 2);
                p1 += __shfl_down_sync(0xFFFFFFFFu, p1, 1);
                p1 += __shfl_down_sync(0xFFFFFFFFu, p1, 2);
                if (tig == 0 && valid) {
                    atomicAdd(&S0[r], p0);
                    atomicAdd(&S1[r], p1);
                }
            }
        }
    } else {
        #pragma unroll
        for (int mf = 0; mf < 2; mf++) {
            #pragma unroll
            for (int nf = 0; nf < 4; nf++) {
                int c = bn + wn + nf * 8 + tig * 2;
                float bv0 = 0.f, bv1 = 0.f;
                if constexpr (MODE == 1) { bv0 = bias1[c]; bv1 = bias1[c + 1]; }
                #pragma unroll
                for (int half_i = 0; half_i < 2; half_i++) {
                    int r = bm + wm + mf * 16 + gid + half_i * 8;
                    if (r >= Nr) continue;
                    float v0 = acc[mf][nf][half_i * 2 + 0];
                    float v1 = acc[mf][nf][half_i * 2 + 1];
                    if constexpr (MODE == 5) {
                        if (c < H2P) {
                            long base = (long)r * H2P + c;
                            Cb[base]     = __float2half(v0);
                            Cb[base + 1] = __float2half(v1);
                        } else {
                            long base = (long)r * H2P + (c - H2P);
                            Cb2[base]     = __float2half(v0);
                            Cb2[base + 1] = __float2half(v1);
                        }
                    } else {
                        long base = (long)r * M + c;
                        v0 = fmaxf(v0 + bv0, 0.f);
                        v1 = fmaxf(v1 + bv1, 0.f);
                        Cb[base]     = __float2half(v0);
                        Cb[base + 1] = __float2half(v1);
                    }
                }
            }
        }
    }
}

// ---------------------------------------------------------------------------
// Merged score + agg1. Score over fp8 z: 8 lanes/edge, 4 edges/warp,
// one uint4 (16 fp8) per lane, lanes 0..6 live (112 bytes).
// Blocks [SB,..): out[i] = s0[i] + Agg(s1)[i] + b3.
// ---------------------------------------------------------------------------
#define SB 2048
__global__ void score_agg1_kernel(const uint8_t* __restrict__ z8, const int* __restrict__ ei,
                                  const int* __restrict__ nei, int E_, float* __restrict__ accum,
                                  const float* __restrict__ s0, const float* __restrict__ s1,
                                  const int2* __restrict__ csr_sn,
                                  const int* __restrict__ rowptr, const float* __restrict__ b3,
                                  float* __restrict__ out, int n) {
    if (blockIdx.x >= SB) {
        int i = (blockIdx.x - SB) * 256 + threadIdx.x;
        if (i < n) {
            float a = 0.f;
            int end = rowptr[i + 1];
            for (int j = rowptr[i]; j < end; j++) {
                int2 sn = csr_sn[j];
                a += s1[sn.x] * __int_as_float(sn.y);
            }
            out[i] = s0[i] + a + b3[0];
        }
        return;
    }
    int lane = threadIdx.x & 31;
    int grp = lane >> 3;           // 0..3: edge within quad
    int l = lane & 7;              // lane within edge group
    int warp_global = (blockIdx.x * blockDim.x + threadIdx.x) >> 5;
    int nwarps = (SB * 256) >> 5;
    int total = 2 * E_;
    float psum = 0.f, nsum = 0.f;
    for (int t0 = warp_global * 4; t0 < total; t0 += nwarps * 4) {
        int t = t0 + grp;
        float dot = 0.f;
        int which = 0;
        if (t < total) {
            which = (t >= E_);
            const int* p = which ? nei : ei;
            int e = which ? t - E_ : t;
            int a = p[e], b = p[e + E_];
            if (l < 7) {
                uint4 ua = *reinterpret_cast<const uint4*>(z8 + (long)a * ZSB + l * 16);
                uint4 ub = *reinterpret_cast<const uint4*>(z8 + (long)b * ZSB + l * 16);
                const __nv_fp8x2_storage_t* pa =
                    reinterpret_cast<const __nv_fp8x2_storage_t*>(&ua);
                const __nv_fp8x2_storage_t* pb =
                    reinterpret_cast<const __nv_fp8x2_storage_t*>(&ub);
                #pragma unroll
                for (int q = 0; q < 8; q++) {
                    __half2_raw ra = __nv_cvt_fp8x2_to_halfraw2(pa[q], __NV_E4M3);
                    __half2_raw rb = __nv_cvt_fp8x2_to_halfraw2(pb[q], __NV_E4M3);
                    float2 fa = __half22float2(*reinterpret_cast<__half2*>(&ra));
                    float2 fb = __half22float2(*reinterpret_cast<__half2*>(&rb));
                    dot += fa.x * fb.x + fa.y * fb.y;
                }
            }
        }
        dot += __shfl_down_sync(0xFFFFFFFFu, dot, 4);
        dot += __shfl_down_sync(0xFFFFFFFFu, dot, 2);
        dot += __shfl_down_sync(0xFFFFFFFFu, dot, 1);
        if (l == 0 && t < total) {
            float sig = 1.f / (1.f + expf(-dot));
            if (which) nsum += logf(1.f - sig + 1e-15f);
            else       psum += logf(sig + 1e-15f);
        }
    }
    // group leaders at lanes 0,8,16,24
    psum += __shfl_down_sync(0xFFFFFFFFu, psum, 16);
    psum += __shfl_down_sync(0xFFFFFFFFu, psum, 8);
    nsum += __shfl_down_sync(0xFFFFFFFFu, nsum, 16);
    nsum += __shfl_down_sync(0xFFFFFFFFu, nsum, 8);
    __shared__ float redp[32], redn[32];
    if (lane == 0) { redp[threadIdx.x >> 5] = psum; redn[threadIdx.x >> 5] = nsum; }
    __syncthreads();
    if (threadIdx.x < 32) {
        int nw = blockDim.x >> 5;
        float vp = (threadIdx.x < nw) ? redp[threadIdx.x] : 0.f;
        float vn = (threadIdx.x < nw) ? redn[threadIdx.x] : 0.f;
        #pragma unroll
        for (int dd = 16; dd; dd >>= 1) {
            vp += __shfl_down_sync(0xFFFFFFFFu, vp, dd);
            vn += __shfl_down_sync(0xFFFFFFFFu, vn, dd);
        }
        if (threadIdx.x == 0) {
            atomicAdd(&accum[0], vp);
            atomicAdd(&accum[1], vn);
        }
    }
}

// Tiny tail: out[n]=loss, out[n+1]=c1, out[n+2]=c2.
__global__ void final_kernel(const float* __restrict__ accum, const float* __restrict__ c1,
                             const float* __restrict__ c2, float* __restrict__ out,
                             int n, float invE) {
    if (threadIdx.x == 0) {
        out[n] = -(accum[0] + accum[1]) * invE;
        out[n + 1] = c1[0];
        out[n + 2] = c2[0];
    }
}

// ---------------------------------------------------------------------------
// Launch
// ---------------------------------------------------------------------------
extern "C" void kernel_launch(void* const* d_in, const int* in_sizes, int n_in,
                              void* d_out, int out_size) {
    const float* x      = (const float*)d_in[0];
    const int*   ei     = (const int*)d_in[1];
    const int*   nei    = (const int*)d_in[2];
    const float* W1_0   = (const float*)d_in[3];
    const float* W1_1   = (const float*)d_in[4];
    const float* b1     = (const float*)d_in[5];
    const float* W2_0   = (const float*)d_in[6];
    const float* W2_1   = (const float*)d_in[7];
    const float* b2     = (const float*)d_in[8];
    const float* W3_0   = (const float*)d_in[9];
    const float* W3_1   = (const float*)d_in[10];
    const float* b3     = (const float*)d_in[11];
    const float* lin1_W = (const float*)d_in[12];
    const float* lin1_b = (const float*)d_in[13];
    const float* lin2_W = (const float*)d_in[14];
    const float* lin2_b = (const float*)d_in[15];
    const float* c1     = (const float*)d_in[16];
    const float* c2     = (const float*)d_in[17];
    float* out = (float*)d_out;

    int n = in_sizes[0] / F_IN;   // 50000
    int e = in_sizes[1] / 2;      // 800000

    Scratch* sp = nullptr;
    cudaGetSymbolAddress((void**)&sp, g_s);

    const int* src = ei;
    const int* dst = ei + e;

    int nb_n = (n + 255) / 256;
    int nb_e = (e + 255) / 256;
    int agg_blocks = (n * 32 + 255) / 256;
    int nb_scan = (n + 1023) / 1024;
    int gy = (n + 127) / 128;
    int nbA = (n * FP + 255) / 256;
    int nbC = (CTOT + 255) / 256;

    // Setup (zero + pad-x + weight conversions)
    setup_kernel<<<nbA + nbC, 256>>>(x, W1_0, W1_1, W2_0, W2_1,
                                     lin1_W, lin2_W, b1, b2, lin1_b, lin2_b,
                                     W3_0, W3_1, n, nbA);

    // Histogram (strictly after zeroing)
    hist_kernel<<<nb_e, 256>>>(src, dst, sp->deg, sp->cnt, e);

    // CSR build
    scan1dis_kernel<<<nb_scan, 1024>>>(sp->cnt, sp->deg, sp->rowptr, sp->bsum, sp->dis, n);
    scan23_kernel<<<nb_scan, 1024>>>(sp->rowptr, sp->cursor, sp->bsum, nb_scan, n);
    fill_kernel<<<nb_e, 256>>>(src, dst, sp->dis, sp->cursor, sp->csr_sn, e);

    // Stage 1 aggregation (fp16 source) -> xpA cols [64,128)
    aggx_kernel<<<agg_blocks, 256>>>(sp->csr_sn, sp->rowptr, sp->xpA, n);

    // G1 (MODE 1): h(fp16) = relu([xp|tx1] @ W1cat + b1)   K=128, M=320
    hgemm_kernel<1, false><<<dim3(H1P / 64, gy), 256>>>(
        sp->xpA, KA1, KA1, sp->W1c, nullptr, nullptr, nullptr,
        sp->b1p, nullptr, nullptr, nullptr, nullptr,
        nullptr, nullptr, sp->h_fp, nullptr, nullptr, n, H1P);

    // G2 (MODE 5): hW21f(fp16) | hW20h(fp16) = h @ [W2_1 | W2_0]   K=320, M=256
    hgemm_kernel<5, false><<<dim3(M2B / 64, gy), 256>>>(
        sp->h_fp, KH, KH, sp->W2c, nullptr, nullptr, nullptr,
        nullptr, nullptr, nullptr, nullptr, nullptr,
        nullptr, nullptr, sp->hW21f, sp->hW20h, nullptr, n, M2B);

    // agg2(fp16) = Agg(hW21f) over fp16 rows (live cols 0..99)
    agg2h_kernel<<<agg_blocks, 256>>>(sp->hW21f, sp->csr_sn, sp->rowptr, sp->agg2h, n);

    // G4 (MODE 4): s0/s1 += xm . W3_{0,1}; z8 = fp8(z) compact;
    //              x1 = relu(hW20h + agg2h + b2) in epilogue
    hgemm_kernel<4, true><<<dim3(H2P / 64, gy), 256>>>(
        sp->xpA, KA1, FP, sp->L1, sp->L2, sp->hW20h, sp->agg2h,
        sp->l1bp, sp->l2bp, sp->b2p, sp->w30p, sp->w31p,
        sp->s0, sp->s1, nullptr, nullptr, sp->z8, n, H2P);

    // Losses + node outputs (overlapped in one grid)
    score_agg1_kernel<<<SB + nb_n, 256>>>(sp->z8, ei, nei, e, sp->accum,
                                          sp->s0, sp->s1, sp->csr_sn,
                                          sp->rowptr, b3, out, n);
    final_kernel<<<1, 32>>>(sp->accum, c1, c2, out, n, 1.0f / (float)e);
}

// round 16
// speedup vs baseline: 1.0590x; 1.0060x over previous
#include <cuda_runtime.h>
#include <cuda_fp16.h>
#include <cuda_fp8.h>
#include <cstdint>
#include <math.h>

#define NN 50000
#define EE 800000
#define F_IN 58
#define FP 64
#define H1 300
#define H2 100
#define H1P 320
#define H2P 128
#define KA1 128   // GEMM1 K: [xp|tx1]
#define KH 320    // padded K for fused stage-2 GEMM
#define M2B 256   // fused stage-2 GEMM logical N: [W2_1|W2_0]
#define ZSB 112   // z row stride in BYTES (fp8); cols 100..111 == 0

// ---------------------------------------------------------------------------
// Scratch (device-global, no runtime allocation).
// ---------------------------------------------------------------------------
struct alignas(16) Scratch {
    int   deg[NN];
    int   cnt[NN];
    int   rowptr[NN + 4];
    int   cursor[NN];
    int2  csr_sn[EE];        // packed (src, norm-bits) in CSR(dst) order
    int   bsum[64];
    float dis[NN];
    __half xpA[NN * KA1];    // [x_fp16 | Agg(x)] fp16
    __half h_fp[NN * KH];    // relu(cheb1) fp16, [N,320]
    __half hW21f[NN * H2P];  // h @ W2_1 (fp16, gathered by agg2)
    __half hW20h[NN * H2P];  // h @ W2_0 (fp16)
    __half agg2h[NN * H2P];  // Agg(hW21f) fp16
    uint8_t z8[NN * ZSB];    // compact fp8(e4m3) z
    __half W1c[KA1 * H1P];   // [128,320]
    __half W2c[KH * M2B];    // [320,256]
    __half L1[FP * H2P];     // [64,128]
    __half L2[FP * H2P];
    float b1p[H1P], b2p[H2P], l1bp[H2P], l2bp[H2P];
    float w30p[H2P], w31p[H2P];
    float s0[NN], s1[NN];
    float accum[2];
};
__device__ Scratch g_s;

// ---------------------------------------------------------------------------
// PTX helpers
// ---------------------------------------------------------------------------
__device__ __forceinline__ uint32_t smem_u32(const void* p) {
    return (uint32_t)__cvta_generic_to_shared(p);
}
__device__ __forceinline__ void ldm_x4(uint32_t* r, uint32_t addr) {
    asm volatile("ldmatrix.sync.aligned.m8n8.x4.shared.b16 {%0,%1,%2,%3}, [%4];"
                 : "=r"(r[0]), "=r"(r[1]), "=r"(r[2]), "=r"(r[3]) : "r"(addr));
}
__device__ __forceinline__ void ldm_x4_t(uint32_t* r, uint32_t addr) {
    asm volatile("ldmatrix.sync.aligned.m8n8.x4.trans.shared.b16 {%0,%1,%2,%3}, [%4];"
                 : "=r"(r[0]), "=r"(r[1]), "=r"(r[2]), "=r"(r[3]) : "r"(addr));
}
__device__ __forceinline__ void mma_fp16(float* c, const uint32_t* a, const uint32_t* b) {
    asm volatile("mma.sync.aligned.m16n8k16.row.col.f32.f16.f16.f32 "
                 "{%0,%1,%2,%3}, {%4,%5,%6,%7}, {%8,%9}, {%0,%1,%2,%3};"
                 : "+f"(c[0]), "+f"(c[1]), "+f"(c[2]), "+f"(c[3])
                 : "r"(a[0]), "r"(a[1]), "r"(a[2]), "r"(a[3]), "r"(b[0]), "r"(b[1]));
}
__device__ __forceinline__ void cp_async16(uint32_t dst, const void* src, bool pred) {
    int sz = pred ? 16 : 0;
    asm volatile("cp.async.cg.shared.global [%0], [%1], 16, %2;\n"
                 :: "r"(dst), "l"(src), "r"(sz));
}
__device__ __forceinline__ void cp_commit() {
    asm volatile("cp.async.commit_group;\n");
}
template <int N>
__device__ __forceinline__ void cp_wait() {
    asm volatile("cp.async.wait_group %0;\n" :: "n"(N));
}

// ---------------------------------------------------------------------------
// zero_kernel: tiny ordering anchor (runs before the atomics in setup2).
// ---------------------------------------------------------------------------
__global__ void zero_kernel(int n) {
    int i = blockIdx.x * blockDim.x + threadIdx.x;
    if (i < n) { g_s.deg[i] = 0; g_s.cnt[i] = 0; g_s.s0[i] = 0.f; g_s.s1[i] = 0.f; }
    if (i < 2) g_s.accum[i] = 0.f;
}

// ---------------------------------------------------------------------------
// setup2: hist blocks [0,nbE) ∥ pad-x blocks [nbE,nbE+nbA) ∥ conv blocks rest.
// All partitions low-smem/high-occupancy; zeroing done in PRIOR launch.
// ---------------------------------------------------------------------------
#define CN1 (KA1 * H1P)
#define CN2 (KH * M2B)
#define CN3 (FP * H2P)
#define CTOT (CN1 + CN2 + 2 * CN3 + H1P + 5 * H2P)
__global__ void setup2_kernel(const float* __restrict__ x,
                              const int* __restrict__ src, const int* __restrict__ dst,
                              const float* __restrict__ W10, const float* __restrict__ W11,
                              const float* __restrict__ W20, const float* __restrict__ W21,
                              const float* __restrict__ l1W, const float* __restrict__ l2W,
                              const float* __restrict__ b1, const float* __restrict__ b2,
                              const float* __restrict__ l1b, const float* __restrict__ l2b,
                              const float* __restrict__ W30, const float* __restrict__ W31,
                              int n, int e, int nbE, int nbA) {
    if (blockIdx.x < (unsigned)nbE) {
        int i = blockIdx.x * 256 + threadIdx.x;
        if (i < e) {
            atomicAdd(&g_s.deg[src[i]], 1);
            atomicAdd(&g_s.cnt[dst[i]], 1);
        }
        return;
    }
    if (blockIdx.x < (unsigned)(nbE + nbA)) {
        int i = (blockIdx.x - nbE) * 256 + threadIdx.x;
        if (i < n * FP) {
            int r = i >> 6, f = i & 63;
            float v = (f < F_IN) ? x[(long)r * F_IN + f] : 0.f;
            g_s.xpA[(long)r * KA1 + f] = __float2half(v);
        }
        return;
    }
    int i = (blockIdx.x - nbE - nbA) * 256 + threadIdx.x;
    if (i < CN1) {
        int k = i / H1P, m = i % H1P;
        float v = 0.f;
        if (m < H1) {
            if (k < F_IN) v = W10[k * H1 + m];
            else if (k >= FP && k < FP + F_IN) v = W11[(k - FP) * H1 + m];
        }
        g_s.W1c[i] = __float2half(v);
        return;
    }
    i -= CN1;
    if (i < CN2) {
        int k = i / M2B, m = i % M2B;
        float v = 0.f;
        if (k < H1) {
            if (m < H2P) { if (m < H2) v = W21[k * H2 + m]; }
            else { int mm = m - H2P; if (mm < H2) v = W20[k * H2 + mm]; }
        }
        g_s.W2c[i] = __float2half(v);
        return;
    }
    i -= CN2;
    if (i < CN3) {
        int k = i >> 7, m = i & 127;
        float v = (k < F_IN && m < H2) ? l1W[m * F_IN + k] : 0.f;
        g_s.L1[i] = __float2half(v);
        return;
    }
    i -= CN3;
    if (i < CN3) {
        int k = i >> 7, m = i & 127;
        float v = (k < F_IN && m < H2) ? l2W[m * F_IN + k] : 0.f;
        g_s.L2[i] = __float2half(v);
        return;
    }
    i -= CN3;
    if (i < H1P) { g_s.b1p[i] = (i < H1) ? b1[i] : 0.f; return; }
    i -= H1P;
    if (i < H2P) { g_s.b2p[i] = (i < H2) ? b2[i] : 0.f; return; }
    i -= H2P;
    if (i < H2P) { g_s.l1bp[i] = (i < H2) ? l1b[i] : 0.f; return; }
    i -= H2P;
    if (i < H2P) { g_s.l2bp[i] = (i < H2) ? l2b[i] : 0.f; return; }
    i -= H2P;
    if (i < H2P) { g_s.w30p[i] = (i < H2) ? W30[i] : 0.f; return; }
    i -= H2P;
    if (i < H2P) { g_s.w31p[i] = (i < H2) ? W31[i] : 0.f; return; }
}

// scan stage 1 (+ dis folded in)
__global__ void scan1dis_kernel(const int* __restrict__ cnt, const int* __restrict__ deg,
                                int* __restrict__ rowptr, int* __restrict__ bsum,
                                float* __restrict__ dis, int n) {
    __shared__ int warp_sums[32];
    int tid = threadIdx.x;
    int i = blockIdx.x * 1024 + tid;
    if (i < n) {
        int d = deg[i];
        dis[i] = (d > 0) ? (1.0f / sqrtf((float)d)) : 0.0f;
    }
    int v = (i < n) ? cnt[i] : 0;
    int x = v;
    #pragma unroll
    for (int d = 1; d < 32; d <<= 1) {
        int y = __shfl_up_sync(0xFFFFFFFFu, x, d);
        if ((tid & 31) >= d) x += y;
    }
    if ((tid & 31) == 31) warp_sums[tid >> 5] = x;
    __syncthreads();
    if (tid < 32) {
        int y = warp_sums[tid];
        int zz = y;
        #pragma unroll
        for (int d = 1; d < 32; d <<= 1) {
            int w = __shfl_up_sync(0xFFFFFFFFu, zz, d);
            if (tid >= d) zz += w;
        }
        warp_sums[tid] = zz - y;
    }
    __syncthreads();
    int incl = x + warp_sums[tid >> 5];
    if (i < n) rowptr[i] = incl - v;
    if (tid == 1023) bsum[blockIdx.x] = incl;
}

// scan stages 2+3 merged.
__global__ void scan23_kernel(int* __restrict__ rowptr, int* __restrict__ cursor,
                              const int* __restrict__ bsum, int nb, int n) {
    __shared__ int s_off;
    int b = blockIdx.x;
    if (threadIdx.x == 0) {
        int run = 0;
        for (int j = 0; j < b; j++) run += bsum[j];
        s_off = run;
        if (b == nb - 1) rowptr[n] = run + bsum[b];
    }
    __syncthreads();
    int i = b * 1024 + threadIdx.x;
    if (i < n) {
        int v = rowptr[i] + s_off;
        rowptr[i] = v;
        cursor[i] = v;
    }
}

// fill: single packed int2 scattered store per edge.
__global__ void fill_kernel(const int* __restrict__ src, const int* __restrict__ dst,
                            const float* __restrict__ dis, int* __restrict__ cursor,
                            int2* __restrict__ csr_sn, int e) {
    int i = blockIdx.x * blockDim.x + threadIdx.x;
    if (i < e) {
        int s = src[i], d = dst[i];
        int p = atomicAdd(&cursor[d], 1);
        float w = -(dis[s] * dis[d]);
        csr_sn[p] = make_int2(s, __float_as_int(w));
    }
}

// ---------------------------------------------------------------------------
// Stage-1 aggregation over fp16 x rows (cols [0,58) of xpA) -> xpA cols [64,128).
// ---------------------------------------------------------------------------
__global__ void aggx_kernel(const int2* __restrict__ csr_sn, const int* __restrict__ rowptr,
                            __half* __restrict__ xpA, int n) {
    int node = (blockIdx.x * blockDim.x + threadIdx.x) >> 5;
    int lane = threadIdx.x & 31;
    if (node >= n) return;
    int beg = rowptr[node], end = rowptr[node + 1];
    float a0 = 0.f, a1 = 0.f;
    bool act = (lane < 29);
    for (int j = beg; j < end; j++) {
        int2 sn = csr_sn[j];
        float w = __int_as_float(sn.y);
        if (act) {
            __half2 v = *reinterpret_cast<const __half2*>(xpA + (long)sn.x * KA1 + 2 * lane);
            float2 f = __half22float2(v);
            a0 += f.x * w;
            a1 += f.y * w;
        }
    }
    long o = (long)node * KA1 + FP + 2 * lane;
    *reinterpret_cast<__half2*>(xpA + o) =
        __floats2half2_rn(act ? a0 : 0.f, act ? a1 : 0.f);
}

// ---------------------------------------------------------------------------
// agg2 over fp16 rows [N,128], live cols [0,100): out fp16 [N,128].
// ---------------------------------------------------------------------------
__global__ void agg2h_kernel(const __half* __restrict__ val, const int2* __restrict__ csr_sn,
                             const int* __restrict__ rowptr, __half* __restrict__ out, int n) {
    int node = (blockIdx.x * blockDim.x + threadIdx.x) >> 5;
    int lane = threadIdx.x & 31;
    if (node >= n) return;
    int beg = rowptr[node], end = rowptr[node + 1];
    float a0 = 0.f, a1 = 0.f, a2 = 0.f, a3 = 0.f;
    bool act2 = (lane < 18);
    for (int j = beg; j < end; j++) {
        int2 sn = csr_sn[j];
        float w = __int_as_float(sn.y);
        const __half2* vr = reinterpret_cast<const __half2*>(val + (long)sn.x * H2P);
        float2 f0 = __half22float2(vr[lane]);
        a0 += f0.x * w; a1 += f0.y * w;
        if (act2) {
            float2 f1 = __half22float2(vr[32 + lane]);
            a2 += f1.x * w; a3 += f1.y * w;
        }
    }
    __half2* orow = reinterpret_cast<__half2*>(out + (long)node * H2P);
    orow[lane]      = __floats2half2_rn(a0, a1);
    orow[32 + lane] = __floats2half2_rn(act2 ? a2 : 0.f, act2 ? a3 : 0.f);
}

// ---------------------------------------------------------------------------
// Double-buffered (cp.async) fp16 tensor-core GEMM.
// MODE 1: Cb = fp16(relu(acc + bias1)), stride M
// MODE 4: x1 = relu(addmh + addm2h + bias3)
//         xm = x1 + relu(acc1 + bias1); s0 += xm.w30, s1 += xm.w31 (atomic)
//         Z8 = fp8(x1 + relu(acc2 + bias2)) at byte stride ZSB, cols < 100
// MODE 5: c<128 -> Cb[r*128+c] = fp16(acc); else Cb2[r*128+(c-128)] = fp16(acc)
// ---------------------------------------------------------------------------
template <int MODE, bool DUALOUT>
__global__ __launch_bounds__(256)
void hgemm_kernel(const __half* __restrict__ A, int lda, int K,
                  const __half* __restrict__ B1, const __half* __restrict__ B2,
                  const __half* __restrict__ addmh, const __half* __restrict__ addm2h,
                  const float* __restrict__ bias1, const float* __restrict__ bias2,
                  const float* __restrict__ bias3,
                  const float* __restrict__ w30, const float* __restrict__ w31,
                  float* __restrict__ S0, float* __restrict__ S1,
                  __half* __restrict__ Cb, __half* __restrict__ Cb2,
                  uint8_t* __restrict__ Z8,
                  int Nr, int M) {
    __shared__ __align__(16) __half As[2][128][40];
    __shared__ __align__(16) __half Bs[2][32][72];
    __shared__ __align__(16) __half Bs2[DUALOUT ? 2 : 1][32][72];

    int tid = threadIdx.x;
    int bm = blockIdx.y * 128, bn = blockIdx.x * 64;
    int lane = tid & 31, wid = tid >> 5;
    int wm = (wid >> 1) * 32, wn = (wid & 1) * 32;

    int a_row = tid >> 1;
    int a_seg = (tid & 1) * 2;
    int b_row = tid >> 3, b_seg = tid & 7;

    float acc[2][4][4];
    float acc2[2][4][4];
    #pragma unroll
    for (int mf = 0; mf < 2; mf++)
        #pragma unroll
        for (int nf = 0; nf < 4; nf++)
            #pragma unroll
            for (int q = 0; q < 4; q++) { acc[mf][nf][q] = 0.f; acc2[mf][nf][q] = 0.f; }

    int nIter = K >> 5;

    auto load_stage = [&](int it, int stg) {
        int k0 = it << 5;
        bool ok = (bm + a_row) < Nr;
        long aoff = (long)(bm + a_row) * lda + k0 + a_seg * 8;
        cp_async16(smem_u32(&As[stg][a_row][a_seg * 8]), A + aoff, ok);
        cp_async16(smem_u32(&As[stg][a_row][(a_seg + 1) * 8]), A + aoff + 8, ok);
        long boff = (long)(k0 + b_row) * M + bn + b_seg * 8;
        cp_async16(smem_u32(&Bs[stg][b_row][b_seg * 8]), B1 + boff, true);
        if constexpr (DUALOUT)
            cp_async16(smem_u32(&Bs2[stg][b_row][b_seg * 8]), B2 + boff, true);
    };

    load_stage(0, 0);
    cp_commit();

    for (int it = 0; it < nIter; it++) {
        int stg = it & 1;
        if (it > 0) __syncthreads();
        if (it + 1 < nIter) {
            load_stage(it + 1, (it + 1) & 1);
            cp_commit();
            cp_wait<1>();
        } else {
            cp_wait<0>();
        }
        __syncthreads();

        #pragma unroll
        for (int s = 0; s < 32; s += 16) {
            uint32_t a[2][4];
            #pragma unroll
            for (int mf = 0; mf < 2; mf++) {
                int row = wm + mf * 16 + (lane & 15);
                int col = s + ((lane >> 4) << 3);
                ldm_x4(a[mf], smem_u32(&As[stg][row][col]));
            }
            int kr = s + (lane & 7) + (lane & 8);
            int nshift = (lane >> 4) << 3;
            uint32_t b[4][2];
            #pragma unroll
            for (int g = 0; g < 2; g++) {
                int nc = wn + g * 16 + nshift;
                uint32_t r[4];
                ldm_x4_t(r, smem_u32(&Bs[stg][kr][nc]));
                b[g * 2][0] = r[0]; b[g * 2][1] = r[1];
                b[g * 2 + 1][0] = r[2]; b[g * 2 + 1][1] = r[3];
            }
            #pragma unroll
            for (int mf = 0; mf < 2; mf++)
                #pragma unroll
                for (int nf = 0; nf < 4; nf++)
                    mma_fp16(acc[mf][nf], a[mf], b[nf]);
            if constexpr (DUALOUT) {
                uint32_t b2[4][2];
                #pragma unroll
                for (int g = 0; g < 2; g++) {
                    int nc = wn + g * 16 + nshift;
                    uint32_t r[4];
                    ldm_x4_t(r, smem_u32(&Bs2[stg][kr][nc]));
                    b2[g * 2][0] = r[0]; b2[g * 2][1] = r[1];
                    b2[g * 2 + 1][0] = r[2]; b2[g * 2 + 1][1] = r[3];
                }
                #pragma unroll
                for (int mf = 0; mf < 2; mf++)
                    #pragma unroll
                    for (int nf = 0; nf < 4; nf++)
                        mma_fp16(acc2[mf][nf], a[mf], b2[nf]);
            }
        }
    }

    // --- epilogue
    int gid = lane >> 2, tig = lane & 3;
    if constexpr (MODE == 4) {
        #pragma unroll
        for (int mf = 0; mf < 2; mf++) {
            #pragma unroll
            for (int half_i = 0; half_i < 2; half_i++) {
                int r = bm + wm + mf * 16 + gid + half_i * 8;
                bool valid = (r < Nr);
                float p0 = 0.f, p1 = 0.f;
                #pragma unroll
                for (int nf = 0; nf < 4; nf++) {
                    int c = bn + wn + nf * 8 + tig * 2;
                    if (valid) {
                        long base = (long)r * H2P + c;
                        float ah0 = __half2float(addmh[base]);
                        float ah1 = __half2float(addmh[base + 1]);
                        float g0 = __half2float(addm2h[base]);
                        float g1 = __half2float(addm2h[base + 1]);
                        float x10 = fmaxf(ah0 + g0 + bias3[c],     0.f);
                        float x11 = fmaxf(ah1 + g1 + bias3[c + 1], 0.f);
                        float xm0 = x10 + fmaxf(acc[mf][nf][half_i * 2 + 0] + bias1[c],     0.f);
                        float xm1 = x11 + fmaxf(acc[mf][nf][half_i * 2 + 1] + bias1[c + 1], 0.f);
                        p0 += xm0 * w30[c] + xm1 * w30[c + 1];
                        p1 += xm0 * w31[c] + xm1 * w31[c + 1];
                        if (c < ZSB) {
                            float z0 = 0.f, z1 = 0.f;
                            if (c < H2) {
                                z0 = x10 + fmaxf(acc2[mf][nf][half_i * 2 + 0] + bias2[c],     0.f);
                                z1 = x11 + fmaxf(acc2[mf][nf][half_i * 2 + 1] + bias2[c + 1], 0.f);
                            }
                            __nv_fp8x2_storage_t pk = __nv_cvt_float2_to_fp8x2(
                                make_float2(z0, z1), __NV_SATFINITE, __NV_E4M3);
                            *reinterpret_cast<unsigned short*>(Z8 + (long)r * ZSB + c) = pk;
                        }
                    }
                }
                p0 += __shfl_down_sync(0xFFFFFFFFu, p0, 1);
                p0 += __shfl_down_sync(0xFFFFFFFFu, p0, 2);
                p1 += __shfl_down_sync(0xFFFFFFFFu, p1, 1);
                p1 += __shfl_down_sync(0xFFFFFFFFu, p1, 2);
                if (tig == 0 && valid) {
                    atomicAdd(&S0[r], p0);
                    atomicAdd(&S1[r], p1);
                }
            }
        }
    } else {
        #pragma unroll
        for (int mf = 0; mf < 2; mf++) {
            #pragma unroll
            for (int nf = 0; nf < 4; nf++) {
                int c = bn + wn + nf * 8 + tig * 2;
                float bv0 = 0.f, bv1 = 0.f;
                if constexpr (MODE == 1) { bv0 = bias1[c]; bv1 = bias1[c + 1]; }
                #pragma unroll
                for (int half_i = 0; half_i < 2; half_i++) {
                    int r = bm + wm + mf * 16 + gid + half_i * 8;
                    if (r >= Nr) continue;
                    float v0 = acc[mf][nf][half_i * 2 + 0];
                    float v1 = acc[mf][nf][half_i * 2 + 1];
                    if constexpr (MODE == 5) {
                        if (c < H2P) {
                            long base = (long)r * H2P + c;
                            Cb[base]     = __float2half(v0);
                            Cb[base + 1] = __float2half(v1);
                        } else {
                            long base = (long)r * H2P + (c - H2P);
                            Cb2[base]     = __float2half(v0);
                            Cb2[base + 1] = __float2half(v1);
                        }
                    } else {
                        long base = (long)r * M + c;
                        v0 = fmaxf(v0 + bv0, 0.f);
                        v1 = fmaxf(v1 + bv1, 0.f);
                        Cb[base]     = __float2half(v0);
                        Cb[base + 1] = __float2half(v1);
                    }
                }
            }
        }
    }
}

// ---------------------------------------------------------------------------
// Merged score + agg1. Score over fp8 z: 8 lanes/edge, 4 edges/warp,
// one uint4 (16 fp8) per lane, lanes 0..6 live (112 bytes).
// Blocks [SB,..): out[i] = s0[i] + Agg(s1)[i] + b3.
// ---------------------------------------------------------------------------
#define SB 2048
__global__ void score_agg1_kernel(const uint8_t* __restrict__ z8, const int* __restrict__ ei,
                                  const int* __restrict__ nei, int E_, float* __restrict__ accum,
                                  const float* __restrict__ s0, const float* __restrict__ s1,
                                  const int2* __restrict__ csr_sn,
                                  const int* __restrict__ rowptr, const float* __restrict__ b3,
                                  float* __restrict__ out, int n) {
    if (blockIdx.x >= SB) {
        int i = (blockIdx.x - SB) * 256 + threadIdx.x;
        if (i < n) {
            float a = 0.f;
            int end = rowptr[i + 1];
            for (int j = rowptr[i]; j < end; j++) {
                int2 sn = csr_sn[j];
                a += s1[sn.x] * __int_as_float(sn.y);
            }
            out[i] = s0[i] + a + b3[0];
        }
        return;
    }
    int lane = threadIdx.x & 31;
    int grp = lane >> 3;
    int l = lane & 7;
    int warp_global = (blockIdx.x * blockDim.x + threadIdx.x) >> 5;
    int nwarps = (SB * 256) >> 5;
    int total = 2 * E_;
    float psum = 0.f, nsum = 0.f;
    for (int t0 = warp_global * 4; t0 < total; t0 += nwarps * 4) {
        int t = t0 + grp;
        float dot = 0.f;
        int which = 0;
        if (t < total) {
            which = (t >= E_);
            const int* p = which ? nei : ei;
            int e = which ? t - E_ : t;
            int a = p[e], b = p[e + E_];
            if (l < 7) {
                uint4 ua = *reinterpret_cast<const uint4*>(z8 + (long)a * ZSB + l * 16);
                uint4 ub = *reinterpret_cast<const uint4*>(z8 + (long)b * ZSB + l * 16);
                const __nv_fp8x2_storage_t* pa =
                    reinterpret_cast<const __nv_fp8x2_storage_t*>(&ua);
                const __nv_fp8x2_storage_t* pb =
                    reinterpret_cast<const __nv_fp8x2_storage_t*>(&ub);
                #pragma unroll
                for (int q = 0; q < 8; q++) {
                    __half2_raw ra = __nv_cvt_fp8x2_to_halfraw2(pa[q], __NV_E4M3);
                    __half2_raw rb = __nv_cvt_fp8x2_to_halfraw2(pb[q], __NV_E4M3);
                    float2 fa = __half22float2(*reinterpret_cast<__half2*>(&ra));
                    float2 fb = __half22float2(*reinterpret_cast<__half2*>(&rb));
                    dot += fa.x * fb.x + fa.y * fb.y;
                }
            }
        }
        dot += __shfl_down_sync(0xFFFFFFFFu, dot, 4);
        dot += __shfl_down_sync(0xFFFFFFFFu, dot, 2);
        dot += __shfl_down_sync(0xFFFFFFFFu, dot, 1);
        if (l == 0 && t < total) {
            float sig = 1.f / (1.f + expf(-dot));
            if (which) nsum += logf(1.f - sig + 1e-15f);
            else       psum += logf(sig + 1e-15f);
        }
    }
    psum += __shfl_down_sync(0xFFFFFFFFu, psum, 16);
    psum += __shfl_down_sync(0xFFFFFFFFu, psum, 8);
    nsum += __shfl_down_sync(0xFFFFFFFFu, nsum, 16);
    nsum += __shfl_down_sync(0xFFFFFFFFu, nsum, 8);
    __shared__ float redp[32], redn[32];
    if (lane == 0) { redp[threadIdx.x >> 5] = psum; redn[threadIdx.x >> 5] = nsum; }
    __syncthreads();
    if (threadIdx.x < 32) {
        int nw = blockDim.x >> 5;
        float vp = (threadIdx.x < nw) ? redp[threadIdx.x] : 0.f;
        float vn = (threadIdx.x < nw) ? redn[threadIdx.x] : 0.f;
        #pragma unroll
        for (int dd = 16; dd; dd >>= 1) {
            vp += __shfl_down_sync(0xFFFFFFFFu, vp, dd);
            vn += __shfl_down_sync(0xFFFFFFFFu, vn, dd);
        }
        if (threadIdx.x == 0) {
            atomicAdd(&accum[0], vp);
            atomicAdd(&accum[1], vn);
        }
    }
}

// Tiny tail: out[n]=loss, out[n+1]=c1, out[n+2]=c2.
__global__ void final_kernel(const float* __restrict__ accum, const float* __restrict__ c1,
                             const float* __restrict__ c2, float* __restrict__ out,
                             int n, float invE) {
    if (threadIdx.x == 0) {
        out[n] = -(accum[0] + accum[1]) * invE;
        out[n + 1] = c1[0];
        out[n + 2] = c2[0];
    }
}

// ---------------------------------------------------------------------------
// Launch
// ---------------------------------------------------------------------------
extern "C" void kernel_launch(void* const* d_in, const int* in_sizes, int n_in,
                              void* d_out, int out_size) {
    const float* x      = (const float*)d_in[0];
    const int*   ei     = (const int*)d_in[1];
    const int*   nei    = (const int*)d_in[2];
    const float* W1_0   = (const float*)d_in[3];
    const float* W1_1   = (const float*)d_in[4];
    const float* b1     = (const float*)d_in[5];
    const float* W2_0   = (const float*)d_in[6];
    const float* W2_1   = (const float*)d_in[7];
    const float* b2     = (const float*)d_in[8];
    const float* W3_0   = (const float*)d_in[9];
    const float* W3_1   = (const float*)d_in[10];
    const float* b3     = (const float*)d_in[11];
    const float* lin1_W = (const float*)d_in[12];
    const float* lin1_b = (const float*)d_in[13];
    const float* lin2_W = (const float*)d_in[14];
    const float* lin2_b = (const float*)d_in[15];
    const float* c1     = (const float*)d_in[16];
    const float* c2     = (const float*)d_in[17];
    float* out = (float*)d_out;

    int n = in_sizes[0] / F_IN;   // 50000
    int e = in_sizes[1] / 2;      // 800000

    Scratch* sp = nullptr;
    cudaGetSymbolAddress((void**)&sp, g_s);

    const int* src = ei;
    const int* dst = ei + e;

    int nb_n = (n + 255) / 256;
    int nb_e = (e + 255) / 256;
    int agg_blocks = (n * 32 + 255) / 256;
    int nb_scan = (n + 1023) / 1024;
    int gy = (n + 127) / 128;
    int nbA = (n * FP + 255) / 256;
    int nbC = (CTOT + 255) / 256;

    // 1. zero (ordering anchor for histogram atomics)
    zero_kernel<<<nb_n, 256>>>(n);

    // 2. setup2: hist ∥ pad-x ∥ weight conv (independent block partitions)
    setup2_kernel<<<nb_e + nbA + nbC, 256>>>(x, src, dst, W1_0, W1_1, W2_0, W2_1,
                                             lin1_W, lin2_W, b1, b2, lin1_b, lin2_b,
                                             W3_0, W3_1, n, e, nb_e, nbA);

    // 3-5. CSR build
    scan1dis_kernel<<<nb_scan, 1024>>>(sp->cnt, sp->deg, sp->rowptr, sp->bsum, sp->dis, n);
    scan23_kernel<<<nb_scan, 1024>>>(sp->rowptr, sp->cursor, sp->bsum, nb_scan, n);
    fill_kernel<<<nb_e, 256>>>(src, dst, sp->dis, sp->cursor, sp->csr_sn, e);

    // 6. Stage 1 aggregation (fp16 source) -> xpA cols [64,128)
    aggx_kernel<<<agg_blocks, 256>>>(sp->csr_sn, sp->rowptr, sp->xpA, n);

    // 7. G1 (MODE 1): h(fp16) = relu([xp|tx1] @ W1cat + b1)   K=128, M=320
    hgemm_kernel<1, false><<<dim3(H1P / 64, gy), 256>>>(
        sp->xpA, KA1, KA1, sp->W1c, nullptr, nullptr, nullptr,
        sp->b1p, nullptr, nullptr, nullptr, nullptr,
        nullptr, nullptr, sp->h_fp, nullptr, nullptr, n, H1P);

    // 8. G2 (MODE 5): hW21f | hW20h = h @ [W2_1 | W2_0]   K=320, M=256
    hgemm_kernel<5, false><<<dim3(M2B / 64, gy), 256>>>(
        sp->h_fp, KH, KH, sp->W2c, nullptr, nullptr, nullptr,
        nullptr, nullptr, nullptr, nullptr, nullptr,
        nullptr, nullptr, sp->hW21f, sp->hW20h, nullptr, n, M2B);

    // 9. agg2(fp16) = Agg(hW21f)
    agg2h_kernel<<<agg_blocks, 256>>>(sp->hW21f, sp->csr_sn, sp->rowptr, sp->agg2h, n);

    // 10. G4 (MODE 4): s0/s1 += xm . W3_{0,1}; z8 = fp8(z);
    //                  x1 = relu(hW20h + agg2h + b2) in epilogue
    hgemm_kernel<4, true><<<dim3(H2P / 64, gy), 256>>>(
        sp->xpA, KA1, FP, sp->L1, sp->L2, sp->hW20h, sp->agg2h,
        sp->l1bp, sp->l2bp, sp->b2p, sp->w30p, sp->w31p,
        sp->s0, sp->s1, nullptr, nullptr, sp->z8, n, H2P);

    // 11. Losses + node outputs (overlapped in one grid)
    score_agg1_kernel<<<SB + nb_n, 256>>>(sp->z8, ei, nei, e, sp->accum,
                                          sp->s0, sp->s1, sp->csr_sn,
                                          sp->rowptr, b3, out, n);
    final_kernel<<<1, 32>>>(sp->accum, c1, c2, out, n, 1.0f / (float)e);
}